// round 7
// baseline (speedup 1.0000x reference)
#include <cuda_runtime.h>
#include <cuda_bf16.h>
#include <math.h>
#include <cstdint>

#define BDIM   2
#define SDIM   2048
#define NSTATE 1024
#define NHEAD  16
#define HDIM   64
#define MROWS  (BDIM*SDIM)            // 4096

constexpr float SCALE_QK = 0.35355339059327373f;  // 64^-0.25

// ---------------- scratch (static device globals; no allocs allowed) --------
__device__ float g_Q [BDIM*NHEAD*SDIM*HDIM];   // [b][h][s][d], pre-scaled
__device__ float g_K [BDIM*NHEAD*SDIM*HDIM];
__device__ float g_V [BDIM*NHEAD*SDIM*HDIM];
__device__ float g_WV[MROWS*NSTATE];           // [b][s][h*d] row-major

__device__ __nv_bfloat16 g_xh [MROWS*NSTATE];
__device__ __nv_bfloat16 g_xl [MROWS*NSTATE];
__device__ __nv_bfloat16 g_WVh[MROWS*NSTATE];
__device__ __nv_bfloat16 g_WVl[MROWS*NSTATE];
__device__ __nv_bfloat16 g_Wth[4*NSTATE*NSTATE];  // transposed weights [n][k], order q,k,v,o
__device__ __nv_bfloat16 g_Wtl[4*NSTATE*NSTATE];

// ---------------- conversion helpers ---------------------------------------
__device__ __forceinline__ void split_bf16(float v, __nv_bfloat16& h, __nv_bfloat16& l) {
    h = __float2bfloat16_rn(v);
    l = __float2bfloat16_rn(v - __bfloat162float(h));
}

__global__ void convert_x_kernel(const float* __restrict__ x) {
    size_t i = (size_t)blockIdx.x * 256 + threadIdx.x;
    float4 v = ((const float4*)x)[i];
    __nv_bfloat16 h[4], l[4];
    split_bf16(v.x, h[0], l[0]); split_bf16(v.y, h[1], l[1]);
    split_bf16(v.z, h[2], l[2]); split_bf16(v.w, h[3], l[3]);
    ((uint2*)g_xh)[i] = *(uint2*)h;
    ((uint2*)g_xl)[i] = *(uint2*)l;
}
__global__ void convert_wv_kernel() {
    size_t i = (size_t)blockIdx.x * 256 + threadIdx.x;
    float4 v = ((const float4*)g_WV)[i];
    __nv_bfloat16 h[4], l[4];
    split_bf16(v.x, h[0], l[0]); split_bf16(v.y, h[1], l[1]);
    split_bf16(v.z, h[2], l[2]); split_bf16(v.w, h[3], l[3]);
    ((uint2*)g_WVh)[i] = *(uint2*)h;
    ((uint2*)g_WVl)[i] = *(uint2*)l;
}

// Transpose + split 4 weight matrices: Wt[n][k] = W[k][n]
__global__ void transpose_convert(const float* __restrict__ W0, const float* __restrict__ W1,
                                  const float* __restrict__ W2, const float* __restrict__ W3) {
    __shared__ float T[32][33];
    int w = blockIdx.z;
    const float* W = (w == 0) ? W0 : (w == 1) ? W1 : (w == 2) ? W2 : W3;
    int n0 = blockIdx.x * 32, k0 = blockIdx.y * 32;
    int tx = threadIdx.x, ty = threadIdx.y;
#pragma unroll
    for (int r = 0; r < 4; r++) {
        int kl = ty + 8 * r;
        T[kl][tx] = W[(size_t)(k0 + kl) * NSTATE + n0 + tx];
    }
    __syncthreads();
    size_t base = (size_t)w * NSTATE * NSTATE;
#pragma unroll
    for (int r = 0; r < 4; r++) {
        int nl = ty + 8 * r;
        float v = T[tx][nl];
        __nv_bfloat16 h, l;
        split_bf16(v, h, l);
        size_t o = base + (size_t)(n0 + nl) * NSTATE + k0 + tx;
        g_Wth[o] = h;
        g_Wtl[o] = l;
    }
}

// ---------------- warp-mma bf16 hi/lo GEMM ----------------------------------
// C(4096x1024) = A(4096x1024) @ W(1024x1024); B stored transposed [n][k].
// CTA tile 128x128, BK=32, 8 warps (2m x 4n), warp tile 64x32 via m16n8k16.
__device__ __forceinline__ void mma16816(float* c, const uint32_t* a, const uint32_t* b) {
    asm volatile(
        "mma.sync.aligned.m16n8k16.row.col.f32.bf16.bf16.f32 "
        "{%0,%1,%2,%3}, {%4,%5,%6,%7}, {%8,%9}, {%0,%1,%2,%3};"
        : "+f"(c[0]), "+f"(c[1]), "+f"(c[2]), "+f"(c[3])
        : "r"(a[0]), "r"(a[1]), "r"(a[2]), "r"(a[3]), "r"(b[0]), "r"(b[1]));
}

#define LDW 40   // padded row length (bf16) for 128x32 tiles

__device__ __forceinline__ void load_tile32(const __nv_bfloat16* __restrict__ src,
                                            int rowBase, int k0,
                                            __nv_bfloat16 (*S)[LDW], int tid) {
#pragma unroll
    for (int i = 0; i < 4; i++) {
        int idx = tid + i * 256;
        int row = idx >> 3, seg = idx & 7;
        uint2 v = *(const uint2*)(src + (size_t)(rowBase + row) * NSTATE + k0 + seg * 4);
        *(uint2*)&S[row][seg * 4] = v;
    }
}

__global__ __launch_bounds__(256)
void gemm_mma(const float* __restrict__ bias, float* __restrict__ Cext,
              float scl, int aSel, int wIdx, int outSel)
{
    __shared__ __nv_bfloat16 Ash[128][LDW], Asl[128][LDW];
    __shared__ __nv_bfloat16 Bsh[128][LDW], Bsl[128][LDW];

    int tid = threadIdx.x;
    int wid = tid >> 5, l = tid & 31;
    int wm = wid >> 2, wn = wid & 3;          // 2 x 4 warp grid
    int mw0 = wm * 64, nw0 = wn * 32;
    int m0 = blockIdx.y * 128, n0 = blockIdx.x * 128;
    int gr = l >> 2, kc = (l & 3) * 2;

    const __nv_bfloat16* A_h = aSel ? g_WVh : g_xh;
    const __nv_bfloat16* A_l = aSel ? g_WVl : g_xl;
    const __nv_bfloat16* B_h = g_Wth + (size_t)wIdx * NSTATE * NSTATE;
    const __nv_bfloat16* B_l = g_Wtl + (size_t)wIdx * NSTATE * NSTATE;

    float c[4][4][4];
#pragma unroll
    for (int mt = 0; mt < 4; mt++)
#pragma unroll
        for (int nt = 0; nt < 4; nt++)
#pragma unroll
            for (int e = 0; e < 4; e++) c[mt][nt][e] = 0.f;

    for (int k0 = 0; k0 < NSTATE; k0 += 32) {
        __syncthreads();
        load_tile32(A_h, m0, k0, Ash, tid);
        load_tile32(A_l, m0, k0, Asl, tid);
        load_tile32(B_h, n0, k0, Bsh, tid);
        load_tile32(B_l, n0, k0, Bsl, tid);
        __syncthreads();

#pragma unroll
        for (int kk = 0; kk < 32; kk += 16) {
            uint32_t bh[4][2], bl[4][2];
#pragma unroll
            for (int nt = 0; nt < 4; nt++) {
                int nr = nw0 + nt * 8 + gr;
                bh[nt][0] = *(uint32_t*)&Bsh[nr][kk + kc];
                bh[nt][1] = *(uint32_t*)&Bsh[nr][kk + kc + 8];
                bl[nt][0] = *(uint32_t*)&Bsl[nr][kk + kc];
                bl[nt][1] = *(uint32_t*)&Bsl[nr][kk + kc + 8];
            }
#pragma unroll
            for (int mt = 0; mt < 4; mt++) {
                int r = mw0 + mt * 16;
                uint32_t ah[4], al[4];
                ah[0] = *(uint32_t*)&Ash[r + gr][kk + kc];
                ah[1] = *(uint32_t*)&Ash[r + gr + 8][kk + kc];
                ah[2] = *(uint32_t*)&Ash[r + gr][kk + kc + 8];
                ah[3] = *(uint32_t*)&Ash[r + gr + 8][kk + kc + 8];
                al[0] = *(uint32_t*)&Asl[r + gr][kk + kc];
                al[1] = *(uint32_t*)&Asl[r + gr + 8][kk + kc];
                al[2] = *(uint32_t*)&Asl[r + gr][kk + kc + 8];
                al[3] = *(uint32_t*)&Asl[r + gr + 8][kk + kc + 8];
#pragma unroll
                for (int nt = 0; nt < 4; nt++) {
                    mma16816(c[mt][nt], ah, bh[nt]);
                    mma16816(c[mt][nt], ah, bl[nt]);
                    mma16816(c[mt][nt], al, bh[nt]);
                }
            }
        }
    }

    // epilogue: v = (acc + bias[n]) * scl
#pragma unroll
    for (int mt = 0; mt < 4; mt++) {
#pragma unroll
        for (int nt = 0; nt < 4; nt++) {
            int n = n0 + nw0 + nt * 8 + kc;          // cols n, n+1
            float b0 = bias ? bias[n] : 0.f;
            float b1 = bias ? bias[n + 1] : 0.f;
#pragma unroll
            for (int half = 0; half < 2; half++) {
                int m = m0 + mw0 + mt * 16 + gr + half * 8;
                float v0 = (c[mt][nt][half * 2 + 0] + b0) * scl;
                float v1 = (c[mt][nt][half * 2 + 1] + b1) * scl;
                if (outSel == 3) {
                    float2* p = (float2*)(Cext + (size_t)m * NSTATE + n);
                    *p = make_float2(v0, v1);
                } else {
                    float* dst = (outSel == 0) ? g_Q : ((outSel == 1) ? g_K : g_V);
                    int b = m >> 11, s = m & (SDIM - 1);
                    int h = n >> 6, d = n & (HDIM - 1);
                    float2* p = (float2*)(dst + ((size_t)(b * NHEAD + h) * SDIM + s) * HDIM + d);
                    *p = make_float2(v0, v1);
                }
            }
        }
    }
}

// ---------------- fill upper-triangle of qk with -1e9 ----------------------
__global__ void fill_mask(float* __restrict__ qk)
{
    size_t i4 = (size_t)blockIdx.x * 256 + threadIdx.x;
    size_t base = i4 * 4;
    int k = (int)(base & (SDIM - 1));
    size_t row = base >> 11;
    int q = (int)(row & (SDIM - 1));
    if (k > q) {
        float4 v = make_float4(-1e9f, -1e9f, -1e9f, -1e9f);
        *(float4*)(qk + base) = v;
    } else if (k + 3 > q) {
#pragma unroll
        for (int e = 0; e < 4; e++)
            if (k + e > q) qk[base + e] = -1e9f;
    }
}

// ---------------- fp32 SIMT flash attention (writes qk logits) -------------
__global__ __launch_bounds__(256, 2)
void flash_kernel(float* __restrict__ qk_out)
{
    int qb = blockIdx.x, h = blockIdx.y, b = blockIdx.z;
    int bh = b * NHEAD + h;
    int q0 = qb * 32;

    __shared__ float Qs[32][68];
    __shared__ float Ks[64][68];
    __shared__ float Vs[64][68];

    int tid = threadIdx.x;
    int r = tid >> 3, l = tid & 7;
    int q = q0 + r;

    const float* Qg = g_Q + (size_t)bh * SDIM * HDIM;
    const float* Kg = g_K + (size_t)bh * SDIM * HDIM;
    const float* Vg = g_V + (size_t)bh * SDIM * HDIM;

#pragma unroll
    for (int i = 0; i < 2; i++) {
        int f = tid + i * 256;
        int row = f >> 4, c = (f & 15) << 2;
        *(float4*)&Qs[row][c] = *(const float4*)(Qg + (size_t)(q0 + row) * HDIM + c);
    }

    float oacc[64];
#pragma unroll
    for (int d = 0; d < 64; d++) oacc[d] = 0.f;
    float mrow = -INFINITY, lrow = 0.f;

    int nTiles = (q0 + 32 + 63) >> 6;
    for (int t = 0; t < nTiles; t++) {
        int k0 = t * 64;
        __syncthreads();
#pragma unroll
        for (int i = 0; i < 4; i++) {
            int f = tid + i * 256;
            int row = f >> 4, c = (f & 15) << 2;
            *(float4*)&Ks[row][c] = *(const float4*)(Kg + (size_t)(k0 + row) * HDIM + c);
            *(float4*)&Vs[row][c] = *(const float4*)(Vg + (size_t)(k0 + row) * HDIM + c);
        }
        __syncthreads();

        float sv[8];
#pragma unroll
        for (int j = 0; j < 8; j++) sv[j] = 0.f;
#pragma unroll
        for (int d = 0; d < 64; d += 4) {
            float4 qv = *(float4*)&Qs[r][d];
#pragma unroll
            for (int j = 0; j < 8; j++) {
                float4 kv = *(float4*)&Ks[j * 8 + l][d];
                sv[j] += qv.x * kv.x + qv.y * kv.y + qv.z * kv.z + qv.w * kv.w;
            }
        }

        float tmax = -INFINITY;
        float* qkrow = qk_out + ((size_t)bh * SDIM + q) * SDIM + k0;
#pragma unroll
        for (int j = 0; j < 8; j++) {
            int kg = k0 + j * 8 + l;
            if (kg > q) sv[j] = -1e9f;
            tmax = fmaxf(tmax, sv[j]);
            qkrow[j * 8 + l] = sv[j];
        }

        tmax = fmaxf(tmax, __shfl_xor_sync(0xffffffffu, tmax, 1));
        tmax = fmaxf(tmax, __shfl_xor_sync(0xffffffffu, tmax, 2));
        tmax = fmaxf(tmax, __shfl_xor_sync(0xffffffffu, tmax, 4));
        float mnew = fmaxf(mrow, tmax);
        float fac = __expf(mrow - mnew);

        float p[8], psum = 0.f;
#pragma unroll
        for (int j = 0; j < 8; j++) { p[j] = __expf(sv[j] - mnew); psum += p[j]; }
        psum += __shfl_xor_sync(0xffffffffu, psum, 1);
        psum += __shfl_xor_sync(0xffffffffu, psum, 2);
        psum += __shfl_xor_sync(0xffffffffu, psum, 4);
        lrow = lrow * fac + psum;
        mrow = mnew;

#pragma unroll
        for (int d = 0; d < 64; d++) oacc[d] *= fac;
#pragma unroll
        for (int j = 0; j < 8; j++) {
            float pj = p[j];
#pragma unroll
            for (int d = 0; d < 64; d += 4) {
                float4 vv = *(float4*)&Vs[j * 8 + l][d];
                oacc[d]     += pj * vv.x;
                oacc[d + 1] += pj * vv.y;
                oacc[d + 2] += pj * vv.z;
                oacc[d + 3] += pj * vv.w;
            }
        }
    }

#pragma unroll
    for (int d = 0; d < 32; d++) {
        float a = oacc[d], bb = oacc[d + 32];
        float send = (l & 4) ? a : bb;
        float recv = __shfl_xor_sync(0xffffffffu, send, 4);
        oacc[d] = ((l & 4) ? bb : a) + recv;
    }
#pragma unroll
    for (int d = 0; d < 16; d++) {
        float a = oacc[d], bb = oacc[d + 16];
        float send = (l & 2) ? a : bb;
        float recv = __shfl_xor_sync(0xffffffffu, send, 2);
        oacc[d] = ((l & 2) ? bb : a) + recv;
    }
#pragma unroll
    for (int d = 0; d < 8; d++) {
        float a = oacc[d], bb = oacc[d + 8];
        float send = (l & 1) ? a : bb;
        float recv = __shfl_xor_sync(0xffffffffu, send, 1);
        oacc[d] = ((l & 1) ? bb : a) + recv;
    }

    float inv = 1.f / lrow;
    float* wvrow = g_WV + ((size_t)(b * SDIM + q) * NHEAD + h) * HDIM + l * 8;
    float4 o0 = make_float4(oacc[0] * inv, oacc[1] * inv, oacc[2] * inv, oacc[3] * inv);
    float4 o1 = make_float4(oacc[4] * inv, oacc[5] * inv, oacc[6] * inv, oacc[7] * inv);
    *(float4*)(wvrow)     = o0;
    *(float4*)(wvrow + 4) = o1;
}

// ---------------------------------------------------------------------------
extern "C" void kernel_launch(void* const* d_in, const int* in_sizes, int n_in,
                              void* d_out, int out_size)
{
    const float* x  = (const float*)d_in[0];
    const float* Wq = (const float*)d_in[2];
    const float* bq = (const float*)d_in[3];
    const float* Wk = (const float*)d_in[4];
    const float* Wv = (const float*)d_in[5];
    const float* bv = (const float*)d_in[6];
    const float* Wo = (const float*)d_in[7];
    const float* bo = (const float*)d_in[8];

    float* out = (float*)d_out;                       // [b,s,1024]
    float* qk  = out + (size_t)BDIM * SDIM * NSTATE;  // [b,h,s,s]

    convert_x_kernel<<<MROWS * NSTATE / 4 / 256, 256>>>(x);
    transpose_convert<<<dim3(32, 32, 4), dim3(32, 8)>>>(Wq, Wk, Wv, Wo);

    dim3 g(NSTATE / 128, MROWS / 128);   // (8, 32)
    gemm_mma<<<g, 256>>>(bq, nullptr, SCALE_QK, 0, 0, 0);
    gemm_mma<<<g, 256>>>(nullptr, nullptr, SCALE_QK, 0, 1, 1);
    gemm_mma<<<g, 256>>>(bv, nullptr, 1.0f, 0, 2, 2);

    size_t qk_f4 = (size_t)BDIM * NHEAD * SDIM * SDIM / 4;
    fill_mask<<<(unsigned)(qk_f4 / 256), 256>>>(qk);

    flash_kernel<<<dim3(SDIM / 32, NHEAD, BDIM), 256>>>(qk);

    convert_wv_kernel<<<MROWS * NSTATE / 4 / 256, 256>>>();
    gemm_mma<<<g, 256>>>(bo, out, 1.0f, 1, 3, 3);
}

// round 8
// speedup vs baseline: 2.1850x; 2.1850x over previous
#include <cuda_runtime.h>
#include <cuda_bf16.h>
#include <math.h>
#include <cstdint>

#define BDIM   2
#define SDIM   2048
#define NSTATE 1024
#define NHEAD  16
#define HDIM   64
#define MROWS  (BDIM*SDIM)            // 4096

constexpr float SCALE_QK = 0.35355339059327373f;  // 64^-0.25

// ---------------- scratch (static device globals; no allocs allowed) --------
__device__ float g_V [BDIM*NHEAD*SDIM*HDIM];   // [b][h][s][d] fp32
__device__ float g_WV[MROWS*NSTATE];           // [b][s][h*d] row-major

__device__ __nv_bfloat16 g_Qh[BDIM*NHEAD*SDIM*HDIM];  // [b][h][s][d] hi/lo, pre-scaled
__device__ __nv_bfloat16 g_Ql[BDIM*NHEAD*SDIM*HDIM];
__device__ __nv_bfloat16 g_Kh[BDIM*NHEAD*SDIM*HDIM];
__device__ __nv_bfloat16 g_Kl[BDIM*NHEAD*SDIM*HDIM];
__device__ __nv_bfloat16 g_Vth[BDIM*NHEAD*HDIM*SDIM]; // [b][h][d][s] hi/lo
__device__ __nv_bfloat16 g_Vtl[BDIM*NHEAD*HDIM*SDIM];

__device__ __nv_bfloat16 g_xh [MROWS*NSTATE];
__device__ __nv_bfloat16 g_xl [MROWS*NSTATE];
__device__ __nv_bfloat16 g_WVh[MROWS*NSTATE];
__device__ __nv_bfloat16 g_WVl[MROWS*NSTATE];
__device__ __nv_bfloat16 g_Wth[4*NSTATE*NSTATE];  // transposed weights [n][k]
__device__ __nv_bfloat16 g_Wtl[4*NSTATE*NSTATE];

// ---------------- helpers ---------------------------------------------------
__device__ __forceinline__ void split_bf16(float v, __nv_bfloat16& h, __nv_bfloat16& l) {
    h = __float2bfloat16_rn(v);
    l = __float2bfloat16_rn(v - __bfloat162float(h));
}
__device__ __forceinline__ void packsplit2(float x, float y, uint32_t& hh, uint32_t& ll) {
    __nv_bfloat16 xh, xl, yh, yl;
    split_bf16(x, xh, xl); split_bf16(y, yh, yl);
    __nv_bfloat162 hv, lv;
    hv.x = xh; hv.y = yh; lv.x = xl; lv.y = yl;
    hh = *(uint32_t*)&hv; ll = *(uint32_t*)&lv;
}
__device__ __forceinline__ void mma16816(float* c, const uint32_t* a, const uint32_t* b) {
    asm volatile(
        "mma.sync.aligned.m16n8k16.row.col.f32.bf16.bf16.f32 "
        "{%0,%1,%2,%3}, {%4,%5,%6,%7}, {%8,%9}, {%0,%1,%2,%3};"
        : "+f"(c[0]), "+f"(c[1]), "+f"(c[2]), "+f"(c[3])
        : "r"(a[0]), "r"(a[1]), "r"(a[2]), "r"(a[3]), "r"(b[0]), "r"(b[1]));
}

// ---------------- conversion kernels ----------------------------------------
__global__ void convert_x_kernel(const float* __restrict__ x) {
    size_t i = (size_t)blockIdx.x * 256 + threadIdx.x;
    float4 v = ((const float4*)x)[i];
    __nv_bfloat16 h[4], l[4];
    split_bf16(v.x, h[0], l[0]); split_bf16(v.y, h[1], l[1]);
    split_bf16(v.z, h[2], l[2]); split_bf16(v.w, h[3], l[3]);
    ((uint2*)g_xh)[i] = *(uint2*)h;
    ((uint2*)g_xl)[i] = *(uint2*)l;
}
__global__ void convert_wv_kernel() {
    size_t i = (size_t)blockIdx.x * 256 + threadIdx.x;
    float4 v = ((const float4*)g_WV)[i];
    __nv_bfloat16 h[4], l[4];
    split_bf16(v.x, h[0], l[0]); split_bf16(v.y, h[1], l[1]);
    split_bf16(v.z, h[2], l[2]); split_bf16(v.w, h[3], l[3]);
    ((uint2*)g_WVh)[i] = *(uint2*)h;
    ((uint2*)g_WVl)[i] = *(uint2*)l;
}

__global__ void transpose_convert(const float* __restrict__ W0, const float* __restrict__ W1,
                                  const float* __restrict__ W2, const float* __restrict__ W3) {
    __shared__ float T[32][33];
    int w = blockIdx.z;
    const float* W = (w == 0) ? W0 : (w == 1) ? W1 : (w == 2) ? W2 : W3;
    int n0 = blockIdx.x * 32, k0 = blockIdx.y * 32;
    int tx = threadIdx.x, ty = threadIdx.y;
#pragma unroll
    for (int r = 0; r < 4; r++) {
        int kl = ty + 8 * r;
        T[kl][tx] = W[(size_t)(k0 + kl) * NSTATE + n0 + tx];
    }
    __syncthreads();
    size_t base = (size_t)w * NSTATE * NSTATE;
#pragma unroll
    for (int r = 0; r < 4; r++) {
        int nl = ty + 8 * r;
        float v = T[tx][nl];
        __nv_bfloat16 h, l;
        split_bf16(v, h, l);
        size_t o = base + (size_t)(n0 + nl) * NSTATE + k0 + tx;
        g_Wth[o] = h;
        g_Wtl[o] = l;
    }
}

// V transpose: g_V[b,h,s,d] fp32 -> g_Vt{h,l}[b,h,d,s] bf16
__global__ void vtrans() {
    __shared__ float T[32][33];
    int bh = blockIdx.z;
    int s0 = blockIdx.x * 32, d0 = blockIdx.y * 32;
    int tx = threadIdx.x, ty = threadIdx.y;
    const float* src = g_V + (size_t)bh * SDIM * HDIM;
#pragma unroll
    for (int r = 0; r < 4; r++)
        T[ty + 8 * r][tx] = src[(size_t)(s0 + ty + 8 * r) * HDIM + d0 + tx];
    __syncthreads();
#pragma unroll
    for (int r = 0; r < 4; r++) {
        int d = d0 + ty + 8 * r;
        float v = T[tx][ty + 8 * r];
        __nv_bfloat16 h, lo;
        split_bf16(v, h, lo);
        size_t o = ((size_t)bh * HDIM + d) * SDIM + s0 + tx;
        g_Vth[o] = h;
        g_Vtl[o] = lo;
    }
}

// ---------------- warp-mma bf16 hi/lo projection GEMM -----------------------
#define LDW 40

__device__ __forceinline__ void load_tile32(const __nv_bfloat16* __restrict__ src,
                                            int rowBase, int k0,
                                            __nv_bfloat16 (*S)[LDW], int tid) {
#pragma unroll
    for (int i = 0; i < 4; i++) {
        int idx = tid + i * 256;
        int row = idx >> 3, seg = idx & 7;
        uint2 v = *(const uint2*)(src + (size_t)(rowBase + row) * NSTATE + k0 + seg * 4);
        *(uint2*)&S[row][seg * 4] = v;
    }
}

__global__ __launch_bounds__(256)
void gemm_mma(const float* __restrict__ bias, float* __restrict__ Cext,
              float scl, int aSel, int wIdx, int outSel)
{
    __shared__ __nv_bfloat16 Ash[128][LDW], Asl[128][LDW];
    __shared__ __nv_bfloat16 Bsh[128][LDW], Bsl[128][LDW];

    int tid = threadIdx.x;
    int wid = tid >> 5, l = tid & 31;
    int wm = wid >> 2, wn = wid & 3;
    int mw0 = wm * 64, nw0 = wn * 32;
    int m0 = blockIdx.y * 128, n0 = blockIdx.x * 128;
    int gr = l >> 2, kc = (l & 3) * 2;

    const __nv_bfloat16* A_h = aSel ? g_WVh : g_xh;
    const __nv_bfloat16* A_l = aSel ? g_WVl : g_xl;
    const __nv_bfloat16* B_h = g_Wth + (size_t)wIdx * NSTATE * NSTATE;
    const __nv_bfloat16* B_l = g_Wtl + (size_t)wIdx * NSTATE * NSTATE;

    float c[4][4][4];
#pragma unroll
    for (int mt = 0; mt < 4; mt++)
#pragma unroll
        for (int nt = 0; nt < 4; nt++)
#pragma unroll
            for (int e = 0; e < 4; e++) c[mt][nt][e] = 0.f;

    for (int k0 = 0; k0 < NSTATE; k0 += 32) {
        __syncthreads();
        load_tile32(A_h, m0, k0, Ash, tid);
        load_tile32(A_l, m0, k0, Asl, tid);
        load_tile32(B_h, n0, k0, Bsh, tid);
        load_tile32(B_l, n0, k0, Bsl, tid);
        __syncthreads();

#pragma unroll
        for (int kk = 0; kk < 32; kk += 16) {
            uint32_t bh[4][2], bl[4][2];
#pragma unroll
            for (int nt = 0; nt < 4; nt++) {
                int nr = nw0 + nt * 8 + gr;
                bh[nt][0] = *(uint32_t*)&Bsh[nr][kk + kc];
                bh[nt][1] = *(uint32_t*)&Bsh[nr][kk + kc + 8];
                bl[nt][0] = *(uint32_t*)&Bsl[nr][kk + kc];
                bl[nt][1] = *(uint32_t*)&Bsl[nr][kk + kc + 8];
            }
#pragma unroll
            for (int mt = 0; mt < 4; mt++) {
                int r = mw0 + mt * 16;
                uint32_t ah[4], al[4];
                ah[0] = *(uint32_t*)&Ash[r + gr][kk + kc];
                ah[1] = *(uint32_t*)&Ash[r + gr + 8][kk + kc];
                ah[2] = *(uint32_t*)&Ash[r + gr][kk + kc + 8];
                ah[3] = *(uint32_t*)&Ash[r + gr + 8][kk + kc + 8];
                al[0] = *(uint32_t*)&Asl[r + gr][kk + kc];
                al[1] = *(uint32_t*)&Asl[r + gr + 8][kk + kc];
                al[2] = *(uint32_t*)&Asl[r + gr][kk + kc + 8];
                al[3] = *(uint32_t*)&Asl[r + gr + 8][kk + kc + 8];
#pragma unroll
                for (int nt = 0; nt < 4; nt++) {
                    mma16816(c[mt][nt], ah, bh[nt]);
                    mma16816(c[mt][nt], ah, bl[nt]);
                    mma16816(c[mt][nt], al, bh[nt]);
                }
            }
        }
    }

    // epilogue: v = (acc + bias[n]) * scl
#pragma unroll
    for (int mt = 0; mt < 4; mt++) {
#pragma unroll
        for (int nt = 0; nt < 4; nt++) {
            int n = n0 + nw0 + nt * 8 + kc;
            float b0 = bias ? bias[n] : 0.f;
            float b1 = bias ? bias[n + 1] : 0.f;
#pragma unroll
            for (int half = 0; half < 2; half++) {
                int m = m0 + mw0 + mt * 16 + gr + half * 8;
                float v0 = (c[mt][nt][half * 2 + 0] + b0) * scl;
                float v1 = (c[mt][nt][half * 2 + 1] + b1) * scl;
                if (outSel == 3) {
                    *(float2*)(Cext + (size_t)m * NSTATE + n) = make_float2(v0, v1);
                } else {
                    int b = m >> 11, s = m & (SDIM - 1);
                    int h2 = n >> 6, d = n & (HDIM - 1);
                    size_t o = ((size_t)(b * NHEAD + h2) * SDIM + s) * HDIM + d;
                    if (outSel == 2) {
                        *(float2*)(g_V + o) = make_float2(v0, v1);
                    } else {
                        uint32_t uh, ul;
                        packsplit2(v0, v1, uh, ul);
                        __nv_bfloat16* dh = outSel ? g_Kh : g_Qh;
                        __nv_bfloat16* dl = outSel ? g_Kl : g_Ql;
                        *(uint32_t*)&dh[o] = uh;
                        *(uint32_t*)&dl[o] = ul;
                    }
                }
            }
        }
    }
}

// ---------------- fill upper-triangle of qk with -1e9 -----------------------
__global__ void fill_mask(float* __restrict__ qk)
{
    size_t t = (size_t)blockIdx.x * 256 + threadIdx.x;
#pragma unroll
    for (int rep = 0; rep < 4; rep++) {
        size_t i4 = t + (size_t)rep * 8388608;      // 2^25 float4s / 4
        size_t base = i4 * 4;
        int k = (int)(base & (SDIM - 1));
        size_t row = base >> 11;
        int q = (int)(row & (SDIM - 1));
        if (k > q) {
            *(float4*)(qk + base) = make_float4(-1e9f, -1e9f, -1e9f, -1e9f);
        } else if (k + 3 > q) {
#pragma unroll
            for (int e = 0; e < 4; e++)
                if (k + e > q) qk[base + e] = -1e9f;
        }
    }
}

// ---------------- tensor-core flash attention (writes qk logits) ------------
// CTA: 128 q-rows, one (b,h). 8 warps, warp w owns rows [w*16, w*16+16).
// K-tiles of 64 keys. S via QK^T (hi/lo), online softmax, PV via Vt (hi/lo).
#define LDK 72
#define FLASH_SMEM ((128*2 + 64*4) * LDK * 2)   // 73728 bytes

__global__ __launch_bounds__(256)
void flash_mma(float* __restrict__ qk_out)
{
    extern __shared__ __nv_bfloat16 sm[];
    __nv_bfloat16* Qh = sm;
    __nv_bfloat16* Ql = Qh + 128 * LDK;
    __nv_bfloat16* Kh = Ql + 128 * LDK;
    __nv_bfloat16* Kl = Kh + 64 * LDK;
    __nv_bfloat16* Vh = Kl + 64 * LDK;
    __nv_bfloat16* Vl = Vh + 64 * LDK;

    int qb = gridDim.x - 1 - blockIdx.x;    // big tiles first (imbalance)
    int hh = blockIdx.y, b = blockIdx.z;
    int bh = b * NHEAD + hh;
    int q0 = qb * 128;
    int tid = threadIdx.x, w = tid >> 5, l = tid & 31;
    int gr = l >> 2, kc = (l & 3) * 2;
    int q0w = q0 + w * 16;

    const __nv_bfloat16* Qhg = g_Qh + (size_t)bh * SDIM * HDIM;
    const __nv_bfloat16* Qlg = g_Ql + (size_t)bh * SDIM * HDIM;
    const __nv_bfloat16* Khg = g_Kh + (size_t)bh * SDIM * HDIM;
    const __nv_bfloat16* Klg = g_Kl + (size_t)bh * SDIM * HDIM;
    const __nv_bfloat16* Vhg = g_Vth + (size_t)bh * HDIM * SDIM;
    const __nv_bfloat16* Vlg = g_Vtl + (size_t)bh * HDIM * SDIM;

    // load Q block [128][64] hi/lo
#pragma unroll
    for (int i = 0; i < 4; i++) {
        int e = tid + i * 256;
        int row = e >> 3, col = (e & 7) * 8;
        *(uint4*)&Qh[row * LDK + col] = *(const uint4*)(Qhg + (size_t)(q0 + row) * HDIM + col);
        *(uint4*)&Ql[row * LDK + col] = *(const uint4*)(Qlg + (size_t)(q0 + row) * HDIM + col);
    }

    float oacc[8][4];
#pragma unroll
    for (int nd = 0; nd < 8; nd++)
#pragma unroll
        for (int e = 0; e < 4; e++) oacc[nd][e] = 0.f;
    float mrow[2] = {-INFINITY, -INFINITY};
    float lrow[2] = {0.f, 0.f};

    int nT = qb * 2 + 2;
    for (int t = 0; t < nT; t++) {
        int k0 = t * 64;
        __syncthreads();
#pragma unroll
        for (int i = 0; i < 2; i++) {
            int e = tid + i * 256;
            int row = e >> 3, col = (e & 7) * 8;
            *(uint4*)&Kh[row * LDK + col] = *(const uint4*)(Khg + (size_t)(k0 + row) * HDIM + col);
            *(uint4*)&Kl[row * LDK + col] = *(const uint4*)(Klg + (size_t)(k0 + row) * HDIM + col);
            *(uint4*)&Vh[row * LDK + col] = *(const uint4*)(Vhg + (size_t)row * SDIM + k0 + col);
            *(uint4*)&Vl[row * LDK + col] = *(const uint4*)(Vlg + (size_t)row * SDIM + k0 + col);
        }
        __syncthreads();
        if (k0 > q0w + 15) continue;   // fully masked for this warp

        // ---- S = Q K^T over this tile ----
        float sacc[8][4];
#pragma unroll
        for (int nt = 0; nt < 8; nt++)
#pragma unroll
            for (int e = 0; e < 4; e++) sacc[nt][e] = 0.f;

#pragma unroll
        for (int kk = 0; kk < 4; kk++) {
            int qr = (w * 16 + gr) * LDK + kk * 16 + kc;
            uint32_t ah[4], al[4];
            ah[0] = *(uint32_t*)&Qh[qr];
            ah[1] = *(uint32_t*)&Qh[qr + 8 * LDK];
            ah[2] = *(uint32_t*)&Qh[qr + 8];
            ah[3] = *(uint32_t*)&Qh[qr + 8 * LDK + 8];
            al[0] = *(uint32_t*)&Ql[qr];
            al[1] = *(uint32_t*)&Ql[qr + 8 * LDK];
            al[2] = *(uint32_t*)&Ql[qr + 8];
            al[3] = *(uint32_t*)&Ql[qr + 8 * LDK + 8];
#pragma unroll
            for (int nt = 0; nt < 8; nt++) {
                int kr = (nt * 8 + gr) * LDK + kk * 16 + kc;
                uint32_t bh2[2], bl2[2];
                bh2[0] = *(uint32_t*)&Kh[kr];
                bh2[1] = *(uint32_t*)&Kh[kr + 8];
                bl2[0] = *(uint32_t*)&Kl[kr];
                bl2[1] = *(uint32_t*)&Kl[kr + 8];
                mma16816(sacc[nt], ah, bh2);
                mma16816(sacc[nt], ah, bl2);
                mma16816(sacc[nt], al, bh2);
            }
        }

        // ---- causal mask (straddling tiles only) ----
        if (k0 + 63 > q0w) {
#pragma unroll
            for (int nt = 0; nt < 8; nt++)
#pragma unroll
                for (int e = 0; e < 4; e++) {
                    int kg = k0 + nt * 8 + kc + (e & 1);
                    int qg = q0w + gr + ((e >> 1) ? 8 : 0);
                    if (kg > qg) sacc[nt][e] = -1e9f;
                }
        }

        // ---- dump qk logits ----
        float* qp = qk_out + ((size_t)bh * SDIM + q0w + gr) * SDIM + k0;
#pragma unroll
        for (int nt = 0; nt < 8; nt++) {
            *(float2*)(qp + nt * 8 + kc) = make_float2(sacc[nt][0], sacc[nt][1]);
            *(float2*)(qp + 8 * SDIM + nt * 8 + kc) = make_float2(sacc[nt][2], sacc[nt][3]);
        }

        // ---- online softmax (2 rows per thread) ----
#pragma unroll
        for (int half = 0; half < 2; half++) {
            int e0 = half * 2;
            float tmax = -INFINITY;
#pragma unroll
            for (int nt = 0; nt < 8; nt++)
                tmax = fmaxf(tmax, fmaxf(sacc[nt][e0], sacc[nt][e0 + 1]));
            tmax = fmaxf(tmax, __shfl_xor_sync(0xffffffffu, tmax, 1));
            tmax = fmaxf(tmax, __shfl_xor_sync(0xffffffffu, tmax, 2));
            float mnew = fmaxf(mrow[half], tmax);
            float fac = __expf(mrow[half] - mnew);
            mrow[half] = mnew;
            float ps = 0.f;
#pragma unroll
            for (int nt = 0; nt < 8; nt++) {
                float p0 = __expf(sacc[nt][e0] - mnew);
                float p1 = __expf(sacc[nt][e0 + 1] - mnew);
                sacc[nt][e0] = p0; sacc[nt][e0 + 1] = p1;
                ps += p0 + p1;
            }
            lrow[half] = lrow[half] * fac + ps;   // per-lane partial; reduced at end
#pragma unroll
            for (int nd = 0; nd < 8; nd++) {
                oacc[nd][e0] *= fac;
                oacc[nd][e0 + 1] *= fac;
            }
        }

        // ---- O += P V (P hi/lo from sacc, V from smem Vt) ----
#pragma unroll
        for (int kk = 0; kk < 4; kk++) {
            uint32_t ph[4], pl[4];
            packsplit2(sacc[2 * kk][0],     sacc[2 * kk][1],     ph[0], pl[0]);
            packsplit2(sacc[2 * kk][2],     sacc[2 * kk][3],     ph[1], pl[1]);
            packsplit2(sacc[2 * kk + 1][0], sacc[2 * kk + 1][1], ph[2], pl[2]);
            packsplit2(sacc[2 * kk + 1][2], sacc[2 * kk + 1][3], ph[3], pl[3]);
#pragma unroll
            for (int nd = 0; nd < 8; nd++) {
                int vr = (nd * 8 + gr) * LDK + kk * 16 + kc;
                uint32_t vh2[2], vl2[2];
                vh2[0] = *(uint32_t*)&Vh[vr];
                vh2[1] = *(uint32_t*)&Vh[vr + 8];
                vl2[0] = *(uint32_t*)&Vl[vr];
                vl2[1] = *(uint32_t*)&Vl[vr + 8];
                mma16816(oacc[nd], ph, vh2);
                mma16816(oacc[nd], ph, vl2);
                mma16816(oacc[nd], pl, vh2);
            }
        }
    }

    // final: reduce l across the 4 lanes of each row, normalize, write WV
#pragma unroll
    for (int half = 0; half < 2; half++) {
        lrow[half] += __shfl_xor_sync(0xffffffffu, lrow[half], 1);
        lrow[half] += __shfl_xor_sync(0xffffffffu, lrow[half], 2);
    }
    float inv0 = 1.f / lrow[0], inv1 = 1.f / lrow[1];
#pragma unroll
    for (int nd = 0; nd < 8; nd++) {
        int d = nd * 8 + kc;
        int q = q0w + gr;
        *(float2*)(g_WV + ((size_t)(b * SDIM + q) * NHEAD + hh) * HDIM + d) =
            make_float2(oacc[nd][0] * inv0, oacc[nd][1] * inv0);
        *(float2*)(g_WV + ((size_t)(b * SDIM + q + 8) * NHEAD + hh) * HDIM + d) =
            make_float2(oacc[nd][2] * inv1, oacc[nd][3] * inv1);
    }
}

// ---------------------------------------------------------------------------
extern "C" void kernel_launch(void* const* d_in, const int* in_sizes, int n_in,
                              void* d_out, int out_size)
{
    const float* x  = (const float*)d_in[0];
    const float* Wq = (const float*)d_in[2];
    const float* bq = (const float*)d_in[3];
    const float* Wk = (const float*)d_in[4];
    const float* Wv = (const float*)d_in[5];
    const float* bv = (const float*)d_in[6];
    const float* Wo = (const float*)d_in[7];
    const float* bo = (const float*)d_in[8];

    float* out = (float*)d_out;                       // [b,s,1024]
    float* qk  = out + (size_t)BDIM * SDIM * NSTATE;  // [b,h,s,s]

    static bool attr_set = false;
    if (!attr_set) {
        cudaFuncSetAttribute(flash_mma, cudaFuncAttributeMaxDynamicSharedMemorySize, FLASH_SMEM);
        attr_set = true;
    }

    convert_x_kernel<<<MROWS * NSTATE / 4 / 256, 256>>>(x);
    transpose_convert<<<dim3(32, 32, 4), dim3(32, 8)>>>(Wq, Wk, Wv, Wo);

    dim3 g(NSTATE / 128, MROWS / 128);   // (8, 32)
    gemm_mma<<<g, 256>>>(bq, nullptr, SCALE_QK, 0, 0, 0);
    gemm_mma<<<g, 256>>>(nullptr, nullptr, SCALE_QK, 0, 1, 1);
    gemm_mma<<<g, 256>>>(bv, nullptr, 1.0f, 0, 2, 2);

    vtrans<<<dim3(SDIM / 32, HDIM / 32, BDIM * NHEAD), dim3(32, 8)>>>();

    fill_mask<<<32768, 256>>>(qk);

    flash_mma<<<dim3(SDIM / 128, NHEAD, BDIM), 256, FLASH_SMEM>>>(qk);

    convert_wv_kernel<<<MROWS * NSTATE / 4 / 256, 256>>>();
    gemm_mma<<<g, 256>>>(bo, out, 1.0f, 1, 3, 3);
}